// round 1
// baseline (speedup 1.0000x reference)
#include <cuda_runtime.h>
#include <math.h>

#define N_NODES 100000
#define N_EDGES 640000
#define N_FEAT  128

// Scratch (device globals; no allocation allowed)
__device__ float g_deg[N_NODES];
__device__ float g_dinv[N_NODES];
__device__ float g_tmp[(size_t)N_NODES * N_FEAT];

// ---------------------------------------------------------------------------
// 1) degree init: self-loop contributes 1 to every node
__global__ void k_init_deg() {
    int i = blockIdx.x * blockDim.x + threadIdx.x;
    if (i < N_NODES) g_deg[i] = 1.0f;
}

// 2) degree accumulation over edge destinations
__global__ void k_deg(const int* __restrict__ ei) {
    int e = blockIdx.x * blockDim.x + threadIdx.x;
    if (e < N_EDGES) atomicAdd(&g_deg[ei[N_EDGES + e]], 1.0f);
}

// 3) dinv = rsqrt(deg); self-loop message tmp[i] = x[i] * dinv[i]^2
//    (also fully initializes g_tmp each replay -> deterministic)
__global__ void k_dinv_selfloop(const float* __restrict__ x) {
    int t = blockIdx.x * blockDim.x + threadIdx.x;
    int node = t >> 5;          // 32 lanes (float4 each) per node row of 128
    int lane = t & 31;
    if (node >= N_NODES) return;
    float d = rsqrtf(g_deg[node]);
    if (lane == 0) g_dinv[node] = d;
    float dd = d * d;
    float4 v = reinterpret_cast<const float4*>(x)[(size_t)node * 32 + lane];
    v.x *= dd; v.y *= dd; v.z *= dd; v.w *= dd;
    reinterpret_cast<float4*>(g_tmp)[(size_t)node * 32 + lane] = v;
}

// 4) edge scatter: warp per edge, lane per float4 of the 128-float row
__global__ void k_scatter(const float* __restrict__ x, const int* __restrict__ ei) {
    int t = blockIdx.x * blockDim.x + threadIdx.x;
    int e = t >> 5;
    int lane = t & 31;
    if (e >= N_EDGES) return;
    int src = ei[e];
    int dst = ei[N_EDGES + e];
    float norm = g_dinv[src] * g_dinv[dst];
    float4 v = reinterpret_cast<const float4*>(x)[(size_t)src * 32 + lane];
    float* drow = g_tmp + (size_t)dst * N_FEAT + lane * 4;
    atomicAdd(drow + 0, v.x * norm);
    atomicAdd(drow + 1, v.y * norm);
    atomicAdd(drow + 2, v.z * norm);
    atomicAdd(drow + 3, v.w * norm);
}

// ---------------------------------------------------------------------------
// 5) Fused GEMM + epilogue:
//    h   = relu(tmp @ W^T + b_conv)         -> written to h_out [N,128]
//    out = sigmoid(h . w_lin + b_lin)       -> written to out  [N]
//
// BM=64 rows per block, full 128 cols, BK=16. 256 threads, each computes
// 8 rows x 4 cols. tid = ty*32 + tx : ty in [0,8) row-group, tx in [0,32)
// col-group (so each warp spans all 128 cols of the same 8-row slab; the
// W_lin row-dot reduces with warp shuffles).
#define BM 64
#define BK 16

__global__ __launch_bounds__(256) void k_gemm_fused(
    const float* __restrict__ W,      // [128,128] row-major (out, in)
    const float* __restrict__ bconv,  // [128]
    const float* __restrict__ wlin,   // [128]
    const float* __restrict__ blin,   // [1]
    float* __restrict__ out,          // [N]
    float* __restrict__ h_out)        // [N,128]
{
    __shared__ float As[BK][BM];     // k-major
    __shared__ float Ws[BK][128];    // k-major

    int tid = threadIdx.x;
    int tx = tid & 31;
    int ty = tid >> 5;
    int row0 = blockIdx.x * BM;

    float acc[8][4];
#pragma unroll
    for (int m = 0; m < 8; m++)
#pragma unroll
        for (int n = 0; n < 4; n++) acc[m][n] = 0.0f;

    int ar = tid >> 2;          // 0..63
    int ac = (tid & 3) * 4;     // 0,4,8,12

    for (int k0 = 0; k0 < N_FEAT; k0 += BK) {
        // load A tile (64 x 16), coalesced float4 per thread
        int grow = row0 + ar;
        float4 av = make_float4(0.f, 0.f, 0.f, 0.f);
        if (grow < N_NODES)
            av = *reinterpret_cast<const float4*>(&g_tmp[(size_t)grow * N_FEAT + k0 + ac]);
        As[ac + 0][ar] = av.x;
        As[ac + 1][ar] = av.y;
        As[ac + 2][ar] = av.z;
        As[ac + 3][ar] = av.w;
        // load W tile (128 x 16), two passes of 64 rows
#pragma unroll
        for (int p = 0; p < 2; p++) {
            int j = ar + p * 64;
            float4 wv = *reinterpret_cast<const float4*>(&W[j * N_FEAT + k0 + ac]);
            Ws[ac + 0][j] = wv.x;
            Ws[ac + 1][j] = wv.y;
            Ws[ac + 2][j] = wv.z;
            Ws[ac + 3][j] = wv.w;
        }
        __syncthreads();

#pragma unroll
        for (int k = 0; k < BK; k++) {
            float4 b4 = *reinterpret_cast<const float4*>(&Ws[k][tx * 4]);
            float4 a0 = *reinterpret_cast<const float4*>(&As[k][ty * 8]);
            float4 a1 = *reinterpret_cast<const float4*>(&As[k][ty * 8 + 4]);
            float a[8] = {a0.x, a0.y, a0.z, a0.w, a1.x, a1.y, a1.z, a1.w};
            float b[4] = {b4.x, b4.y, b4.z, b4.w};
#pragma unroll
            for (int m = 0; m < 8; m++)
#pragma unroll
                for (int n = 0; n < 4; n++)
                    acc[m][n] = fmaf(a[m], b[n], acc[m][n]);
        }
        __syncthreads();
    }

    // epilogue
    float4 bc4 = *reinterpret_cast<const float4*>(&bconv[tx * 4]);
    float4 wl4 = *reinterpret_cast<const float4*>(&wlin[tx * 4]);
    float bcv[4] = {bc4.x, bc4.y, bc4.z, bc4.w};
    float wlv[4] = {wl4.x, wl4.y, wl4.z, wl4.w};
    float blv = blin[0];

#pragma unroll
    for (int m = 0; m < 8; m++) {
        int r = row0 + ty * 8 + m;
        float vals[4];
        float part = 0.0f;
#pragma unroll
        for (int n = 0; n < 4; n++) {
            float v = acc[m][n] + bcv[n];
            v = fmaxf(v, 0.0f);
            vals[n] = v;
            part = fmaf(v, wlv[n], part);
        }
        if (r < N_NODES) {
            float4 hv = make_float4(vals[0], vals[1], vals[2], vals[3]);
            *reinterpret_cast<float4*>(&h_out[(size_t)r * N_FEAT + tx * 4]) = hv;
        }
        // warp reduction over the 32 col-groups (full warp participates)
#pragma unroll
        for (int off = 16; off > 0; off >>= 1)
            part += __shfl_xor_sync(0xffffffffu, part, off);
        if (tx == 0 && r < N_NODES)
            out[r] = 1.0f / (1.0f + expf(-(part + blv)));
    }
}

// ---------------------------------------------------------------------------
extern "C" void kernel_launch(void* const* d_in, const int* in_sizes, int n_in,
                              void* d_out, int out_size) {
    const float* x    = (const float*)d_in[0];
    const int*   ei   = (const int*)d_in[1];
    const float* Wc   = (const float*)d_in[2];
    const float* bc   = (const float*)d_in[3];
    const float* wl   = (const float*)d_in[4];
    const float* bl   = (const float*)d_in[5];

    float* out  = (float*)d_out;            // [N_NODES]  (first tuple element)
    float* hbuf = out + N_NODES;            // [N_NODES, 128]

    k_init_deg<<<(N_NODES + 255) / 256, 256>>>();
    k_deg<<<(N_EDGES + 255) / 256, 256>>>(ei);
    {
        long long t = (long long)N_NODES * 32;
        k_dinv_selfloop<<<(unsigned)((t + 255) / 256), 256>>>(x);
    }
    {
        long long t = (long long)N_EDGES * 32;
        k_scatter<<<(unsigned)((t + 255) / 256), 256>>>(x, ei);
    }
    k_gemm_fused<<<(N_NODES + BM - 1) / BM, 256>>>(Wc, bc, wl, bl, out, hbuf);
}

// round 5
// speedup vs baseline: 1.8893x; 1.8893x over previous
#include <cuda_runtime.h>
#include <math.h>

#define N_NODES 100000
#define N_EDGES 640000
#define N_FEAT  128

#define SCAN_CHUNK 512
#define N_CHUNKS ((N_NODES + SCAN_CHUNK - 1) / SCAN_CHUNK)   // 196

// Scratch (device globals; no allocation allowed)
__device__ int   g_cnt[N_NODES];
__device__ int   g_offs[N_NODES];
__device__ int   g_cursor[N_NODES];
__device__ int   g_bucket[N_EDGES];
__device__ int   g_partial[SCAN_CHUNK];          // >= N_CHUNKS
__device__ float g_dinv[N_NODES];
__device__ float g_tmp[(size_t)N_NODES * N_FEAT];

// ---------------------------------------------------------------------------
// 1) zero destination counts
__global__ void k_init() {
    int i = blockIdx.x * blockDim.x + threadIdx.x;
    if (i < N_NODES) g_cnt[i] = 0;
}

// 2) histogram of edge destinations
__global__ void k_hist(const int* __restrict__ ei) {
    int e = blockIdx.x * blockDim.x + threadIdx.x;
    if (e < N_EDGES) atomicAdd(&g_cnt[ei[N_EDGES + e]], 1);
}

// 3a) per-chunk exclusive scan (chunk = 512), record chunk totals
__global__ __launch_bounds__(SCAN_CHUNK) void k_scan1() {
    __shared__ int s[SCAN_CHUNK];
    int t = threadIdx.x;
    int gid = blockIdx.x * SCAN_CHUNK + t;
    int v = (gid < N_NODES) ? g_cnt[gid] : 0;
    s[t] = v;
    __syncthreads();
#pragma unroll
    for (int d = 1; d < SCAN_CHUNK; d <<= 1) {
        int add = (t >= d) ? s[t - d] : 0;
        __syncthreads();
        s[t] += add;
        __syncthreads();
    }
    if (gid < N_NODES) g_offs[gid] = s[t] - v;          // exclusive within chunk
    if (t == SCAN_CHUNK - 1) g_partial[blockIdx.x] = s[t];
}

// 3b) single-block scan of chunk totals (exclusive)
__global__ __launch_bounds__(SCAN_CHUNK) void k_scan2() {
    __shared__ int s[SCAN_CHUNK];
    int t = threadIdx.x;
    int v = (t < N_CHUNKS) ? g_partial[t] : 0;
    s[t] = v;
    __syncthreads();
#pragma unroll
    for (int d = 1; d < SCAN_CHUNK; d <<= 1) {
        int add = (t >= d) ? s[t - d] : 0;
        __syncthreads();
        s[t] += add;
        __syncthreads();
    }
    if (t < N_CHUNKS) g_partial[t] = s[t] - v;          // exclusive
}

// 3c) add chunk bases; init cursor; compute dinv = rsqrt(deg) (deg = cnt+1)
__global__ void k_scan3() {
    int i = blockIdx.x * blockDim.x + threadIdx.x;
    if (i >= N_NODES) return;
    int o = g_offs[i] + g_partial[i / SCAN_CHUNK];
    g_offs[i] = o;
    g_cursor[i] = o;
    g_dinv[i] = rsqrtf((float)(g_cnt[i] + 1));
}

// 4) bucket fill: CSR-by-destination edge list (stores src per slot)
__global__ void k_fill(const int* __restrict__ ei) {
    int e = blockIdx.x * blockDim.x + threadIdx.x;
    if (e >= N_EDGES) return;
    int dst = ei[N_EDGES + e];
    int pos = atomicAdd(&g_cursor[dst], 1);
    g_bucket[pos] = ei[e];
}

// 5) gather: warp per destination node; lane owns one float4 of the 128-row.
//    acc starts with the self-loop term, then accumulates neighbors from L2.
__global__ __launch_bounds__(256) void k_gather(const float* __restrict__ x) {
    int t = blockIdx.x * blockDim.x + threadIdx.x;
    int node = t >> 5;
    int lane = t & 31;
    if (node >= N_NODES) return;

    const float4* x4 = reinterpret_cast<const float4*>(x);
    float di = g_dinv[node];
    int beg = g_offs[node];
    int cnt = g_cnt[node];

    float4 v = x4[(size_t)node * 32 + lane];
    float dd = di * di;
    float4 acc;
    acc.x = v.x * dd; acc.y = v.y * dd; acc.z = v.z * dd; acc.w = v.w * dd;

    int j = 0;
    // 2-wide software pipeline for memory-level parallelism
    for (; j + 2 <= cnt; j += 2) {
        int s0 = g_bucket[beg + j];
        int s1 = g_bucket[beg + j + 1];
        float n0 = di * g_dinv[s0];
        float n1 = di * g_dinv[s1];
        float4 v0 = x4[(size_t)s0 * 32 + lane];
        float4 v1 = x4[(size_t)s1 * 32 + lane];
        acc.x = fmaf(v0.x, n0, acc.x); acc.y = fmaf(v0.y, n0, acc.y);
        acc.z = fmaf(v0.z, n0, acc.z); acc.w = fmaf(v0.w, n0, acc.w);
        acc.x = fmaf(v1.x, n1, acc.x); acc.y = fmaf(v1.y, n1, acc.y);
        acc.z = fmaf(v1.z, n1, acc.z); acc.w = fmaf(v1.w, n1, acc.w);
    }
    if (j < cnt) {
        int s0 = g_bucket[beg + j];
        float n0 = di * g_dinv[s0];
        float4 v0 = x4[(size_t)s0 * 32 + lane];
        acc.x = fmaf(v0.x, n0, acc.x); acc.y = fmaf(v0.y, n0, acc.y);
        acc.z = fmaf(v0.z, n0, acc.z); acc.w = fmaf(v0.w, n0, acc.w);
    }
    reinterpret_cast<float4*>(g_tmp)[(size_t)node * 32 + lane] = acc;
}

// ---------------------------------------------------------------------------
// 6) Fused GEMM + epilogue:
//    h   = relu(tmp @ W^T + b_conv)   -> h_out [N,128]
//    out = sigmoid(h . w_lin + b_lin) -> out  [N]
#define BM 64
#define BK 16

__global__ __launch_bounds__(256) void k_gemm_fused(
    const float* __restrict__ W,      // [128,128] row-major (out, in)
    const float* __restrict__ bconv,  // [128]
    const float* __restrict__ wlin,   // [128]
    const float* __restrict__ blin,   // [1]
    float* __restrict__ out,          // [N]
    float* __restrict__ h_out)        // [N,128]
{
    __shared__ float As[BK][BM];     // k-major
    __shared__ float Ws[BK][128];    // k-major

    int tid = threadIdx.x;
    int tx = tid & 31;
    int ty = tid >> 5;
    int row0 = blockIdx.x * BM;

    float acc[8][4];
#pragma unroll
    for (int m = 0; m < 8; m++)
#pragma unroll
        for (int n = 0; n < 4; n++) acc[m][n] = 0.0f;

    int ar = tid >> 2;          // 0..63
    int ac = (tid & 3) * 4;     // 0,4,8,12

    for (int k0 = 0; k0 < N_FEAT; k0 += BK) {
        int grow = row0 + ar;
        float4 av = make_float4(0.f, 0.f, 0.f, 0.f);
        if (grow < N_NODES)
            av = *reinterpret_cast<const float4*>(&g_tmp[(size_t)grow * N_FEAT + k0 + ac]);
        As[ac + 0][ar] = av.x;
        As[ac + 1][ar] = av.y;
        As[ac + 2][ar] = av.z;
        As[ac + 3][ar] = av.w;
#pragma unroll
        for (int p = 0; p < 2; p++) {
            int jr = ar + p * 64;
            float4 wv = *reinterpret_cast<const float4*>(&W[jr * N_FEAT + k0 + ac]);
            Ws[ac + 0][jr] = wv.x;
            Ws[ac + 1][jr] = wv.y;
            Ws[ac + 2][jr] = wv.z;
            Ws[ac + 3][jr] = wv.w;
        }
        __syncthreads();

#pragma unroll
        for (int k = 0; k < BK; k++) {
            float4 b4 = *reinterpret_cast<const float4*>(&Ws[k][tx * 4]);
            float4 a0 = *reinterpret_cast<const float4*>(&As[k][ty * 8]);
            float4 a1 = *reinterpret_cast<const float4*>(&As[k][ty * 8 + 4]);
            float a[8] = {a0.x, a0.y, a0.z, a0.w, a1.x, a1.y, a1.z, a1.w};
            float b[4] = {b4.x, b4.y, b4.z, b4.w};
#pragma unroll
            for (int m = 0; m < 8; m++)
#pragma unroll
                for (int n = 0; n < 4; n++)
                    acc[m][n] = fmaf(a[m], b[n], acc[m][n]);
        }
        __syncthreads();
    }

    float4 bc4 = *reinterpret_cast<const float4*>(&bconv[tx * 4]);
    float4 wl4 = *reinterpret_cast<const float4*>(&wlin[tx * 4]);
    float bcv[4] = {bc4.x, bc4.y, bc4.z, bc4.w};
    float wlv[4] = {wl4.x, wl4.y, wl4.z, wl4.w};
    float blv = blin[0];

#pragma unroll
    for (int m = 0; m < 8; m++) {
        int r = row0 + ty * 8 + m;
        float vals[4];
        float part = 0.0f;
#pragma unroll
        for (int n = 0; n < 4; n++) {
            float v = acc[m][n] + bcv[n];
            v = fmaxf(v, 0.0f);
            vals[n] = v;
            part = fmaf(v, wlv[n], part);
        }
        if (r < N_NODES) {
            float4 hv = make_float4(vals[0], vals[1], vals[2], vals[3]);
            *reinterpret_cast<float4*>(&h_out[(size_t)r * N_FEAT + tx * 4]) = hv;
        }
#pragma unroll
        for (int off = 16; off > 0; off >>= 1)
            part += __shfl_xor_sync(0xffffffffu, part, off);
        if (tx == 0 && r < N_NODES)
            out[r] = 1.0f / (1.0f + expf(-(part + blv)));
    }
}

// ---------------------------------------------------------------------------
extern "C" void kernel_launch(void* const* d_in, const int* in_sizes, int n_in,
                              void* d_out, int out_size) {
    const float* x  = (const float*)d_in[0];
    const int*   ei = (const int*)d_in[1];
    const float* Wc = (const float*)d_in[2];
    const float* bc = (const float*)d_in[3];
    const float* wl = (const float*)d_in[4];
    const float* bl = (const float*)d_in[5];

    float* out  = (float*)d_out;            // [N_NODES]
    float* hbuf = out + N_NODES;            // [N_NODES, 128]

    k_init<<<(N_NODES + 255) / 256, 256>>>();
    k_hist<<<(N_EDGES + 255) / 256, 256>>>(ei);
    k_scan1<<<N_CHUNKS, SCAN_CHUNK>>>();
    k_scan2<<<1, SCAN_CHUNK>>>();
    k_scan3<<<(N_NODES + 255) / 256, 256>>>();
    k_fill<<<(N_EDGES + 255) / 256, 256>>>(ei);
    {
        long long t = (long long)N_NODES * 32;
        k_gather<<<(unsigned)((t + 255) / 256), 256>>>(x);
    }
    k_gemm_fused<<<(N_NODES + BM - 1) / BM, 256>>>(Wc, bc, wl, bl, out, hbuf);
}